// round 3
// baseline (speedup 1.0000x reference)
#include <cuda_runtime.h>

// ---------------------------------------------------------------------------
// GAT (2 layers, edge features, H=2 heads x C=16) + mean pool + MLP -> [G,2]
// N<=100352 nodes, E<=3211264 edges (+N self loops), F=128 input features.
// edge_index / batch are int32 (JAX default x64-disabled downcasts int64).
// ---------------------------------------------------------------------------

#define MAXN 100352
#define MAXE 3211264
#define MAXG 256

__device__ __align__(16) float g_h[MAXN * 32];             // transformed features
__device__ __align__(16) float g_out[MAXN * 32];           // aggregation output
__device__ __align__(16) float g_asrc[MAXN * 2];
__device__ __align__(16) float g_adst[MAXN * 2];
__device__ __align__(16) float g_m[MAXN * 2];              // segment max
__device__ __align__(16) float g_s[MAXN * 2];              // segment exp-sum
__device__ __align__(16) float g_alpha[(MAXE + MAXN) * 2]; // per-edge alpha / ex
__device__ __align__(16) float g_scal[8];                  // [0]=esum [1]=mean [2..5]=ce
__device__ __align__(16) float g_pool[MAXG * 32];
__device__ __align__(16) float g_cnt[MAXG];

__device__ __forceinline__ int clampi(int v, int hi) {
    return v < 0 ? 0 : (v >= hi ? hi - 1 : v);
}

__device__ __forceinline__ void atomicMaxF(float* addr, float v) {
    if (v >= 0.f) atomicMax((int*)addr, __float_as_int(v));
    else          atomicMin((unsigned int*)addr, __float_as_uint(v));
}

// ---------------------------------------------------------------------------
// init: zero scalar scratch / pooling accumulators
__global__ void k_init() {
    int t = blockIdx.x * blockDim.x + threadIdx.x;
    if (t < 8) g_scal[t] = 0.f;
    if (t < MAXG) g_cnt[t] = 0.f;
    if (t < MAXG * 32) g_pool[t] = 0.f;
}

// sum of edge_attr -> g_scal[0]
__global__ void k_esum(const float* __restrict__ ea, int E) {
    __shared__ float red[256];
    float acc = 0.f;
    for (int i = blockIdx.x * 256 + threadIdx.x; i < E; i += gridDim.x * 256)
        acc += ea[i];
    red[threadIdx.x] = acc;
    __syncthreads();
    for (int s = 128; s; s >>= 1) {
        if (threadIdx.x < s) red[threadIdx.x] += red[threadIdx.x + s];
        __syncthreads();
    }
    if (threadIdx.x == 0) atomicAdd(&g_scal[0], red[0]);
}

// mean + per-layer per-head edge coefficients ce[h] = sum_c We[h*16+c]*ae[h*16+c]
__global__ void k_prep(const float* __restrict__ We1, const float* __restrict__ ae1,
                       const float* __restrict__ We2, const float* __restrict__ ae2, int E) {
    int t = threadIdx.x;
    if (t == 0) g_scal[1] = g_scal[0] / (float)E;
    if (t < 4) {
        int layer = t >> 1, hh = t & 1;
        const float* We = layer ? We2 : We1;
        const float* ae = layer ? ae2 : ae1;
        float c = 0.f;
        for (int i = 0; i < 16; i++) c += We[hh * 16 + i] * ae[hh * 16 + i];
        g_scal[2 + layer * 2 + hh] = c;
    }
}

// ---------------------------------------------------------------------------
// feature transform: h = in @ W  (+ optional bias+relu on input for layer 2)
// also computes asrc/adst per node, re-inits m/s, zeroes g_out row.
template <int FIN, bool SECOND>
__global__ void k_transform(const float* __restrict__ xin,
                            const float* __restrict__ W,
                            const float* __restrict__ a_src,
                            const float* __restrict__ a_dst,
                            const float* __restrict__ bias, int n) {
    __shared__ float W_sh[FIN * 32];
    __shared__ float x_sh[8][FIN];
    __shared__ float s_as[32], s_ad[32], s_b[32];
    int tid = threadIdx.x;
    for (int i = tid; i < FIN * 32; i += 256) W_sh[i] = W[i];
    if (tid < 32) {
        s_as[tid] = a_src[tid];
        s_ad[tid] = a_dst[tid];
        s_b[tid] = SECOND ? bias[tid] : 0.f;
    }
    __syncthreads();
    int lane = tid & 31, wy = tid >> 5;
    int node = blockIdx.x * 8 + wy;
    if (node >= n) return;
    const float* src = SECOND ? (g_out + node * 32) : (xin + (long long)node * FIN);
    #pragma unroll
    for (int i = lane; i < FIN; i += 32) {
        float v = src[i];
        if (SECOND) v = fmaxf(v + s_b[i], 0.f);
        x_sh[wy][i] = v;
    }
    __syncwarp();
    float acc = 0.f;
    #pragma unroll
    for (int k = 0; k < FIN; k++)
        acc = fmaf(x_sh[wy][k], W_sh[k * 32 + lane], acc);
    g_h[node * 32 + lane] = acc;
    g_out[node * 32 + lane] = 0.f;   // reset aggregation buffer (row already consumed)
    float vs = acc * s_as[lane];
    float vd = acc * s_ad[lane];
    #pragma unroll
    for (int off = 8; off; off >>= 1) {
        vs += __shfl_down_sync(0xffffffffu, vs, off, 16);
        vd += __shfl_down_sync(0xffffffffu, vd, off, 16);
    }
    if ((lane & 15) == 0) {
        int hh = lane >> 4;
        g_asrc[node * 2 + hh] = vs;
        g_adst[node * 2 + hh] = vd;
    }
    if (lane < 2) {
        g_m[node * 2 + lane] = __int_as_float(0xFF800000);  // -inf
        g_s[node * 2 + lane] = 0.f;
    }
}

// ---------------------------------------------------------------------------
// edge pass 1: alpha = leaky_relu(asrc[src]+adst[dst]+ea*ce); segment max
__global__ void k_edge1(const int* __restrict__ ei, const float* __restrict__ ea,
                        int E, int n, int layer) {
    int Et = E + n;
    float c0 = g_scal[2 + layer * 2];
    float c1 = g_scal[3 + layer * 2];
    float mean = g_scal[1];
    for (int e = blockIdx.x * blockDim.x + threadIdx.x; e < Et; e += gridDim.x * blockDim.x) {
        int s, d; float av;
        if (e < E) { s = clampi(ei[e], n); d = clampi(ei[E + e], n); av = ea[e]; }
        else       { s = d = e - E; av = mean; }
        float2 as = ((const float2*)g_asrc)[s];
        float2 ad = ((const float2*)g_adst)[d];
        float a0 = as.x + ad.x + av * c0;
        float a1 = as.y + ad.y + av * c1;
        a0 = a0 > 0.f ? a0 : 0.2f * a0;
        a1 = a1 > 0.f ? a1 : 0.2f * a1;
        ((float2*)g_alpha)[e] = make_float2(a0, a1);
        atomicMaxF(&g_m[d * 2], a0);
        atomicMaxF(&g_m[d * 2 + 1], a1);
    }
}

// edge pass 2: ex = exp(alpha - m[dst]); segment sum
__global__ void k_edge2(const int* __restrict__ ei, int E, int n) {
    int Et = E + n;
    for (int e = blockIdx.x * blockDim.x + threadIdx.x; e < Et; e += gridDim.x * blockDim.x) {
        int d = (e < E) ? clampi(ei[E + e], n) : (e - E);
        float2 al = ((const float2*)g_alpha)[e];
        float2 mm = ((const float2*)g_m)[d];
        float e0 = __expf(al.x - mm.x);
        float e1 = __expf(al.y - mm.y);
        ((float2*)g_alpha)[e] = make_float2(e0, e1);
        atomicAdd((float2*)&g_s[d * 2], make_float2(e0, e1));
    }
}

// edge pass 3: out[dst] += h[src] * (ex / s[dst])
__global__ void k_edge3(const int* __restrict__ ei, int E, int n) {
    int Et = E + n;
    for (int e = blockIdx.x * blockDim.x + threadIdx.x; e < Et; e += gridDim.x * blockDim.x) {
        int s, d;
        if (e < E) { s = clampi(ei[e], n); d = clampi(ei[E + e], n); }
        else       { s = d = e - E; }
        float2 ex = ((const float2*)g_alpha)[e];
        float2 ss = ((const float2*)g_s)[d];
        float att0 = ex.x / (ss.x + 1e-16f);
        float att1 = ex.y / (ss.y + 1e-16f);
        const float4* hv = (const float4*)(g_h + s * 32);
        float4* op = (float4*)(g_out + d * 32);
        #pragma unroll
        for (int j = 0; j < 8; j++) {
            float4 v = hv[j];
            float a = (j < 4) ? att0 : att1;
            v.x *= a; v.y *= a; v.z *= a; v.w *= a;
            atomicAdd(op + j, v);
        }
    }
}

// ---------------------------------------------------------------------------
// global mean pool (fused +b2): accumulate sums + counts per graph
__global__ void k_pool(const int* __restrict__ batch, const float* __restrict__ b2, int n, int G) {
    int node = blockIdx.x * blockDim.x + threadIdx.x;
    if (node >= n) return;
    int g = clampi(batch[node], G);
    const float4* ov = (const float4*)(g_out + node * 32);
    const float4* bv = (const float4*)b2;
    float4* pp = (float4*)(g_pool + g * 32);
    #pragma unroll
    for (int j = 0; j < 8; j++) {
        float4 v = ov[j], b = bv[j];
        v.x += b.x; v.y += b.y; v.z += b.z; v.w += b.w;
        atomicAdd(pp + j, v);
    }
    atomicAdd(&g_cnt[g], 1.f);
}

// predictor MLP: relu(emb @ Wf1 + bf1) @ Wf2 + bf2
__global__ void k_mlp(float* __restrict__ out,
                      const float* __restrict__ Wf1, const float* __restrict__ bf1,
                      const float* __restrict__ Wf2, const float* __restrict__ bf2, int G) {
    int g = blockIdx.x * blockDim.x + threadIdx.x;
    if (g >= G) return;
    float inv = 1.f / fmaxf(g_cnt[g], 1.f);
    float emb[32];
    #pragma unroll
    for (int i = 0; i < 32; i++) emb[i] = g_pool[g * 32 + i] * inv;
    float o0 = bf2[0], o1 = bf2[1];
    for (int j = 0; j < 32; j++) {
        float z = bf1[j];
        #pragma unroll
        for (int i = 0; i < 32; i++) z = fmaf(emb[i], Wf1[i * 32 + j], z);
        z = fmaxf(z, 0.f);
        o0 = fmaf(z, Wf2[j * 2], o0);
        o1 = fmaf(z, Wf2[j * 2 + 1], o1);
    }
    out[g * 2] = o0;
    out[g * 2 + 1] = o1;
}

// ---------------------------------------------------------------------------
extern "C" void kernel_launch(void* const* d_in, const int* in_sizes, int n_in,
                              void* d_out, int out_size) {
    const float* x     = (const float*)d_in[0];
    const int*   ei    = (const int*)d_in[1];
    const float* ea    = (const float*)d_in[2];
    const int*   batch = (const int*)d_in[3];
    const float* W1  = (const float*)d_in[4];
    const float* as1 = (const float*)d_in[5];
    const float* ad1 = (const float*)d_in[6];
    const float* We1 = (const float*)d_in[7];
    const float* ae1 = (const float*)d_in[8];
    const float* b1  = (const float*)d_in[9];
    const float* W2  = (const float*)d_in[10];
    const float* as2 = (const float*)d_in[11];
    const float* ad2 = (const float*)d_in[12];
    const float* We2 = (const float*)d_in[13];
    const float* ae2 = (const float*)d_in[14];
    const float* b2  = (const float*)d_in[15];
    const float* Wf1 = (const float*)d_in[16];
    const float* bf1 = (const float*)d_in[17];
    const float* Wf2 = (const float*)d_in[18];
    const float* bf2 = (const float*)d_in[19];

    int N = in_sizes[0] / 128;
    int E = in_sizes[1] / 2;
    int G = out_size / 2;
    int Et = E + N;
    int eb = (Et + 255) / 256;
    int tb = (N + 7) / 8;

    k_init<<<8, 1024>>>();
    k_esum<<<512, 256>>>(ea, E);
    k_prep<<<1, 32>>>(We1, ae1, We2, ae2, E);

    // layer 1
    k_transform<128, false><<<tb, 256>>>(x, W1, as1, ad1, nullptr, N);
    k_edge1<<<eb, 256>>>(ei, ea, E, N, 0);
    k_edge2<<<eb, 256>>>(ei, E, N);
    k_edge3<<<eb, 256>>>(ei, E, N);

    // layer 2 (input = relu(g_out + b1))
    k_transform<32, true><<<tb, 256>>>(nullptr, W2, as2, ad2, b1, N);
    k_edge1<<<eb, 256>>>(ei, ea, E, N, 1);
    k_edge2<<<eb, 256>>>(ei, E, N);
    k_edge3<<<eb, 256>>>(ei, E, N);

    // pooling + MLP head
    k_pool<<<(N + 255) / 256, 256>>>(batch, b2, N, G);
    k_mlp<<<1, 64>>>((float*)d_out, Wf1, bf1, Wf2, bf2, G);
}

// round 4
// speedup vs baseline: 1.6928x; 1.6928x over previous
#include <cuda_runtime.h>

// ---------------------------------------------------------------------------
// GAT (2 layers, edge features, H=2 heads x C=16) + mean pool + MLP -> [G,2]
// N<=100352 nodes, E<=3211264 edges (+self loops handled implicitly).
// Strategy: build dst-CSR once, then atomic-free warp-per-node aggregation.
// Softmax computed without max-subtraction (shift-invariant; alpha bounded).
// ---------------------------------------------------------------------------

#define MAXN 100352
#define MAXE 3211264
#define MAXG 256
#define NBS ((MAXN + 1023) / 1024)

__device__ __align__(16) float g_h[MAXN * 32];      // transformed features
__device__ __align__(16) float g_out[MAXN * 32];    // aggregation output
__device__ __align__(16) float g_asrc[MAXN * 2];
__device__ __align__(16) float g_adst[MAXN * 2];
__device__ __align__(16) int2  g_csr[MAXE];         // (src, ea_bits) per dst-sorted edge
__device__ int g_rowptr[MAXN + 1];
__device__ int g_cursor[MAXN];
__device__ int g_deg[MAXN];
__device__ int g_bsum[NBS];
__device__ int g_boff[NBS];
__device__ __align__(16) float g_scal[8];           // [0]=esum [1]=mean [2..5]=ce
__device__ __align__(16) float g_pool[MAXG * 32];
__device__ float g_cnt[MAXG];

__device__ __forceinline__ int clampi(int v, int hi) {
    return v < 0 ? 0 : (v >= hi ? hi - 1 : v);
}

// ---------------------------------------------------------------------------
__global__ void k_init(int n) {
    int stride = gridDim.x * blockDim.x;
    for (int i = blockIdx.x * blockDim.x + threadIdx.x; i < n; i += stride)
        g_deg[i] = 0;
    int t = blockIdx.x * blockDim.x + threadIdx.x;
    if (t < 8) g_scal[t] = 0.f;
    if (t < MAXG) g_cnt[t] = 0.f;
    if (t < MAXG * 32) g_pool[t] = 0.f;
}

__global__ void k_esum(const float* __restrict__ ea, int E) {
    __shared__ float red[256];
    float acc = 0.f;
    for (int i = blockIdx.x * 256 + threadIdx.x; i < E; i += gridDim.x * 256)
        acc += ea[i];
    red[threadIdx.x] = acc;
    __syncthreads();
    for (int s = 128; s; s >>= 1) {
        if (threadIdx.x < s) red[threadIdx.x] += red[threadIdx.x + s];
        __syncthreads();
    }
    if (threadIdx.x == 0) atomicAdd(&g_scal[0], red[0]);
}

__global__ void k_prep(const float* __restrict__ We1, const float* __restrict__ ae1,
                       const float* __restrict__ We2, const float* __restrict__ ae2, int E) {
    int t = threadIdx.x;
    if (t == 0) g_scal[1] = g_scal[0] / (float)E;
    if (t < 4) {
        int layer = t >> 1, hh = t & 1;
        const float* We = layer ? We2 : We1;
        const float* ae = layer ? ae2 : ae1;
        float c = 0.f;
        for (int i = 0; i < 16; i++) c += We[hh * 16 + i] * ae[hh * 16 + i];
        g_scal[2 + layer * 2 + hh] = c;
    }
}

// ---------------------------------------------------------------------------
// CSR build: histogram -> scan -> scatter
__global__ void k_hist(const int* __restrict__ ei, int E, int n) {
    for (int e = blockIdx.x * blockDim.x + threadIdx.x; e < E; e += gridDim.x * blockDim.x)
        atomicAdd(&g_deg[clampi(ei[E + e], n)], 1);
}

__global__ void k_scan1(int n) {
    __shared__ int sm[1024];
    int t = threadIdx.x;
    int i = blockIdx.x * 1024 + t;
    int v = (i < n) ? g_deg[i] : 0;
    int x = v;
    sm[t] = x;
    __syncthreads();
    #pragma unroll
    for (int off = 1; off < 1024; off <<= 1) {
        int y = (t >= off) ? sm[t - off] : 0;
        __syncthreads();
        x += y;
        sm[t] = x;
        __syncthreads();
    }
    if (i < n) g_rowptr[i] = x - v;   // exclusive, pre-offset
    if (t == 1023) g_bsum[blockIdx.x] = x;
}

__global__ void k_scan2(int nb) {
    __shared__ int sm[1024];
    int t = threadIdx.x;
    int v = (t < nb) ? g_bsum[t] : 0;
    int x = v;
    sm[t] = x;
    __syncthreads();
    #pragma unroll
    for (int off = 1; off < 1024; off <<= 1) {
        int y = (t >= off) ? sm[t - off] : 0;
        __syncthreads();
        x += y;
        sm[t] = x;
        __syncthreads();
    }
    if (t < nb) g_boff[t] = x - v;    // exclusive
}

__global__ void k_scan3(int n, int E) {
    int i = blockIdx.x * blockDim.x + threadIdx.x;
    if (i < n) {
        int r = g_rowptr[i] + g_boff[i >> 10];
        g_rowptr[i] = r;
        g_cursor[i] = r;
    }
    if (i == 0) g_rowptr[n] = E;
}

__global__ void k_scatter(const int* __restrict__ ei, const float* __restrict__ ea,
                          int E, int n) {
    for (int e = blockIdx.x * blockDim.x + threadIdx.x; e < E; e += gridDim.x * blockDim.x) {
        int s = clampi(ei[e], n);
        int d = clampi(ei[E + e], n);
        int slot = atomicAdd(&g_cursor[d], 1);
        g_csr[slot] = make_int2(s, __float_as_int(ea[e]));
    }
}

// ---------------------------------------------------------------------------
// feature transform: h = in @ W (layer2: in = relu(g_out + b1)).
// Block = 32 nodes; 8 threads per node, each computing 4 output columns via
// LDS.128 on W (4 FMA per 2 LDS). Also emits asrc/adst per node.
template <int FIN, bool SECOND>
__global__ void k_transform(const float* __restrict__ xin,
                            const float* __restrict__ W,
                            const float* __restrict__ a_src,
                            const float* __restrict__ a_dst,
                            const float* __restrict__ bias, int n) {
    constexpr int XS = FIN + 1;                 // pad to kill bank conflicts
    __shared__ float W_sh[FIN * 32];
    __shared__ float x_sh[32 * XS];
    __shared__ float s_as[32], s_ad[32], s_b[32];
    int tid = threadIdx.x;
    for (int i = tid; i < FIN * 32; i += 256) W_sh[i] = W[i];
    if (tid < 32) {
        s_as[tid] = a_src[tid];
        s_ad[tid] = a_dst[tid];
        s_b[tid] = SECOND ? bias[tid] : 0.f;
    }
    __syncthreads();
    int nb = blockIdx.x * 32;
    for (int i = tid; i < 32 * FIN; i += 256) {
        int r = i / FIN, c = i % FIN;
        int node = nb + r;
        float v = 0.f;
        if (node < n) {
            v = SECOND ? g_out[node * 32 + c] : xin[(size_t)node * FIN + c];
            if (SECOND) v = fmaxf(v + s_b[c], 0.f);
        }
        x_sh[r * XS + c] = v;
    }
    __syncthreads();

    int nl = tid >> 3, q = tid & 7;
    int node = nb + nl;
    bool valid = node < n;
    float4 acc = make_float4(0.f, 0.f, 0.f, 0.f);
    const float4* W4 = (const float4*)W_sh;
    #pragma unroll 16
    for (int k = 0; k < FIN; k++) {
        float xv = x_sh[nl * XS + k];
        float4 w = W4[k * 8 + q];
        acc.x = fmaf(xv, w.x, acc.x);
        acc.y = fmaf(xv, w.y, acc.y);
        acc.z = fmaf(xv, w.z, acc.z);
        acc.w = fmaf(xv, w.w, acc.w);
    }
    if (valid)
        ((float4*)(g_h + node * 32))[q] = acc;

    float ps = acc.x * s_as[q * 4] + acc.y * s_as[q * 4 + 1]
             + acc.z * s_as[q * 4 + 2] + acc.w * s_as[q * 4 + 3];
    float pd = acc.x * s_ad[q * 4] + acc.y * s_ad[q * 4 + 1]
             + acc.z * s_ad[q * 4 + 2] + acc.w * s_ad[q * 4 + 3];
    ps += __shfl_down_sync(0xffffffffu, ps, 2, 4);
    ps += __shfl_down_sync(0xffffffffu, ps, 1, 4);
    pd += __shfl_down_sync(0xffffffffu, pd, 2, 4);
    pd += __shfl_down_sync(0xffffffffu, pd, 1, 4);
    if ((q & 3) == 0 && valid) {
        int hh = q >> 2;
        g_asrc[node * 2 + hh] = ps;
        g_adst[node * 2 + hh] = pd;
    }
}

// ---------------------------------------------------------------------------
// fused aggregation: warp per dst node, no atomics.
// out[node] = (sum_e h[src_e] * exp(alpha_e)) / (sum_e exp(alpha_e) + 1e-16)
__global__ void k_agg(int n, int layer) {
    int wg = (blockIdx.x * blockDim.x + threadIdx.x) >> 5;
    if (wg >= n) return;
    int lane = threadIdx.x & 31;
    int node = wg;
    float c0 = g_scal[2 + layer * 2];
    float c1 = g_scal[3 + layer * 2];
    float mean = g_scal[1];
    float2 ad = ((const float2*)g_adst)[node];
    bool hi = lane >= 16;

    float acc = 0.f, s0 = 0.f, s1 = 0.f;
    int beg = g_rowptr[node], end = g_rowptr[node + 1];

    for (int j0 = beg; j0 < end; j0 += 32) {
        int j = j0 + lane;
        bool v = j < end;
        int src = node;
        float av = 0.f;
        if (v) {
            int2 p = g_csr[j];
            src = p.x;
            av = __int_as_float(p.y);
        }
        float2 as = ((const float2*)g_asrc)[src];
        float a0 = as.x + ad.x + av * c0;
        float a1 = as.y + ad.y + av * c1;
        a0 = a0 > 0.f ? a0 : 0.2f * a0;
        a1 = a1 > 0.f ? a1 : 0.2f * a1;
        float ex0 = v ? __expf(a0) : 0.f;
        float ex1 = v ? __expf(a1) : 0.f;
        s0 += ex0;
        s1 += ex1;
        if (end - j0 >= 32) {
            #pragma unroll
            for (int t = 0; t < 32; t++) {
                int st = __shfl_sync(0xffffffffu, src, t);
                float e0 = __shfl_sync(0xffffffffu, ex0, t);
                float e1 = __shfl_sync(0xffffffffu, ex1, t);
                acc = fmaf(g_h[st * 32 + lane], hi ? e1 : e0, acc);
            }
        } else {
            int cnt = end - j0;
            for (int t = 0; t < cnt; t++) {
                int st = __shfl_sync(0xffffffffu, src, t);
                float e0 = __shfl_sync(0xffffffffu, ex0, t);
                float e1 = __shfl_sync(0xffffffffu, ex1, t);
                acc = fmaf(g_h[st * 32 + lane], hi ? e1 : e0, acc);
            }
        }
    }

    // self loop (src = node, ea = mean)
    {
        float2 as = ((const float2*)g_asrc)[node];
        float a0 = as.x + ad.x + mean * c0;
        float a1 = as.y + ad.y + mean * c1;
        a0 = a0 > 0.f ? a0 : 0.2f * a0;
        a1 = a1 > 0.f ? a1 : 0.2f * a1;
        float ex0 = __expf(a0), ex1 = __expf(a1);
        if (lane == 0) { s0 += ex0; s1 += ex1; }
        acc = fmaf(g_h[node * 32 + lane], hi ? ex1 : ex0, acc);
    }

    #pragma unroll
    for (int off = 16; off; off >>= 1) {
        s0 += __shfl_xor_sync(0xffffffffu, s0, off);
        s1 += __shfl_xor_sync(0xffffffffu, s1, off);
    }
    float s = hi ? s1 : s0;
    g_out[node * 32 + lane] = acc / (s + 1e-16f);
}

// ---------------------------------------------------------------------------
__global__ void k_pool(const int* __restrict__ batch, const float* __restrict__ b2,
                       int n, int G) {
    int node = blockIdx.x * blockDim.x + threadIdx.x;
    if (node >= n) return;
    int g = clampi(batch[node], G);
    const float4* ov = (const float4*)(g_out + node * 32);
    const float4* bv = (const float4*)b2;
    float4* pp = (float4*)(g_pool + g * 32);
    #pragma unroll
    for (int j = 0; j < 8; j++) {
        float4 v = ov[j], b = bv[j];
        v.x += b.x; v.y += b.y; v.z += b.z; v.w += b.w;
        atomicAdd(pp + j, v);
    }
    atomicAdd(&g_cnt[g], 1.f);
}

__global__ void k_mlp(float* __restrict__ out,
                      const float* __restrict__ Wf1, const float* __restrict__ bf1,
                      const float* __restrict__ Wf2, const float* __restrict__ bf2, int G) {
    int g = blockIdx.x * blockDim.x + threadIdx.x;
    if (g >= G) return;
    float inv = 1.f / fmaxf(g_cnt[g], 1.f);
    float emb[32];
    #pragma unroll
    for (int i = 0; i < 32; i++) emb[i] = g_pool[g * 32 + i] * inv;
    float o0 = bf2[0], o1 = bf2[1];
    for (int j = 0; j < 32; j++) {
        float z = bf1[j];
        #pragma unroll
        for (int i = 0; i < 32; i++) z = fmaf(emb[i], Wf1[i * 32 + j], z);
        z = fmaxf(z, 0.f);
        o0 = fmaf(z, Wf2[j * 2], o0);
        o1 = fmaf(z, Wf2[j * 2 + 1], o1);
    }
    out[g * 2] = o0;
    out[g * 2 + 1] = o1;
}

// ---------------------------------------------------------------------------
extern "C" void kernel_launch(void* const* d_in, const int* in_sizes, int n_in,
                              void* d_out, int out_size) {
    const float* x     = (const float*)d_in[0];
    const int*   ei    = (const int*)d_in[1];
    const float* ea    = (const float*)d_in[2];
    const int*   batch = (const int*)d_in[3];
    const float* W1  = (const float*)d_in[4];
    const float* as1 = (const float*)d_in[5];
    const float* ad1 = (const float*)d_in[6];
    const float* We1 = (const float*)d_in[7];
    const float* ae1 = (const float*)d_in[8];
    const float* b1  = (const float*)d_in[9];
    const float* W2  = (const float*)d_in[10];
    const float* as2 = (const float*)d_in[11];
    const float* ad2 = (const float*)d_in[12];
    const float* We2 = (const float*)d_in[13];
    const float* ae2 = (const float*)d_in[14];
    const float* b2  = (const float*)d_in[15];
    const float* Wf1 = (const float*)d_in[16];
    const float* bf1 = (const float*)d_in[17];
    const float* Wf2 = (const float*)d_in[18];
    const float* bf2 = (const float*)d_in[19];

    int N = in_sizes[0] / 128;
    int E = in_sizes[1] / 2;
    int G = out_size / 2;
    int nb = (N + 1023) / 1024;
    int tb = (N + 31) / 32;
    int ab = (N + 7) / 8;

    k_init<<<128, 1024>>>(N);
    k_esum<<<512, 256>>>(ea, E);
    k_prep<<<1, 32>>>(We1, ae1, We2, ae2, E);

    // CSR build (by destination)
    k_hist<<<2048, 512>>>(ei, E, N);
    k_scan1<<<nb, 1024>>>(N);
    k_scan2<<<1, 1024>>>(nb);
    k_scan3<<<(N + 1023) / 1024, 1024>>>(N, E);
    k_scatter<<<2048, 512>>>(ei, ea, E, N);

    // layer 1
    k_transform<128, false><<<tb, 256>>>(x, W1, as1, ad1, nullptr, N);
    k_agg<<<ab, 256>>>(N, 0);

    // layer 2 (input = relu(g_out + b1))
    k_transform<32, true><<<tb, 256>>>(nullptr, W2, as2, ad2, b1, N);
    k_agg<<<ab, 256>>>(N, 1);

    // pooling + MLP head
    k_pool<<<(N + 255) / 256, 256>>>(batch, b2, N, G);
    k_mlp<<<1, 64>>>((float*)d_out, Wf1, bf1, Wf2, bf2, G);
}

// round 6
// speedup vs baseline: 1.9858x; 1.1730x over previous
#include <cuda_runtime.h>

// ---------------------------------------------------------------------------
// GAT (2 layers, edge features, H=2 heads x C=16) + mean pool + MLP -> [G,2]
// dst-CSR built once (rank captured in histogram), atomic-free warp-per-node
// aggregation, softmax without max-subtraction (shift-invariant, bounded).
// ---------------------------------------------------------------------------

#define MAXN 100352
#define MAXE 3211264
#define MAXG 256
#define NBS ((MAXN + 1023) / 1024)

__device__ __align__(16) float g_h[MAXN * 32];      // transformed features
__device__ __align__(16) float g_out[MAXN * 32];    // layer-1 aggregation output
__device__ __align__(16) float g_asrc[MAXN * 2];
__device__ __align__(16) float g_adst[MAXN * 2];
__device__ __align__(16) int2  g_csr[MAXE];         // (src, ea_bits), dst-sorted
__device__ int g_rank[MAXE];
__device__ int g_rowptr[MAXN + 1];
__device__ int g_deg[MAXN];
__device__ int g_bsum[NBS];
__device__ int g_boff[NBS];
__device__ __align__(16) float g_scal[8];           // [0]=esum [1]=mean [2..5]=ce
__device__ __align__(16) float g_pool[MAXG * 32];
__device__ float g_cnt[MAXG];

__device__ __forceinline__ int clampi(int v, int hi) {
    return v < 0 ? 0 : (v >= hi ? hi - 1 : v);
}

// ---------------------------------------------------------------------------
__global__ void k_init(int n) {
    int stride = gridDim.x * blockDim.x;
    for (int i = blockIdx.x * blockDim.x + threadIdx.x; i < n; i += stride)
        g_deg[i] = 0;
    int t = blockIdx.x * blockDim.x + threadIdx.x;
    if (t < 8) g_scal[t] = 0.f;
    if (t < MAXG) g_cnt[t] = 0.f;
    if (t < MAXG * 32) g_pool[t] = 0.f;
}

// histogram (captures per-edge rank) + edge_attr sum in one pass
__global__ void k_hist(const int* __restrict__ ei, const float* __restrict__ ea,
                       int E, int n) {
    __shared__ float red[256];
    float acc = 0.f;
    for (int e = blockIdx.x * 256 + threadIdx.x; e < E; e += gridDim.x * 256) {
        int d = clampi(ei[E + e], n);
        g_rank[e] = atomicAdd(&g_deg[d], 1);
        acc += ea[e];
    }
    red[threadIdx.x] = acc;
    __syncthreads();
    for (int s = 128; s; s >>= 1) {
        if (threadIdx.x < s) red[threadIdx.x] += red[threadIdx.x + s];
        __syncthreads();
    }
    if (threadIdx.x == 0) atomicAdd(&g_scal[0], red[0]);
}

__global__ void k_prep(const float* __restrict__ We1, const float* __restrict__ ae1,
                       const float* __restrict__ We2, const float* __restrict__ ae2, int E) {
    int t = threadIdx.x;
    if (t == 0) g_scal[1] = g_scal[0] / (float)E;
    if (t < 4) {
        int layer = t >> 1, hh = t & 1;
        const float* We = layer ? We2 : We1;
        const float* ae = layer ? ae2 : ae1;
        float c = 0.f;
        for (int i = 0; i < 16; i++) c += We[hh * 16 + i] * ae[hh * 16 + i];
        g_scal[2 + layer * 2 + hh] = c;
    }
}

// ---------------------------------------------------------------------------
__global__ void k_scan1(int n) {
    __shared__ int sm[1024];
    int t = threadIdx.x;
    int i = blockIdx.x * 1024 + t;
    int v = (i < n) ? g_deg[i] : 0;
    int x = v;
    sm[t] = x;
    __syncthreads();
    #pragma unroll
    for (int off = 1; off < 1024; off <<= 1) {
        int y = (t >= off) ? sm[t - off] : 0;
        __syncthreads();
        x += y;
        sm[t] = x;
        __syncthreads();
    }
    if (i < n) g_rowptr[i] = x - v;   // exclusive, pre-offset
    if (t == 1023) g_bsum[blockIdx.x] = x;
}

__global__ void k_scan2(int nb) {
    __shared__ int sm[1024];
    int t = threadIdx.x;
    int v = (t < nb) ? g_bsum[t] : 0;
    int x = v;
    sm[t] = x;
    __syncthreads();
    #pragma unroll
    for (int off = 1; off < 1024; off <<= 1) {
        int y = (t >= off) ? sm[t - off] : 0;
        __syncthreads();
        x += y;
        sm[t] = x;
        __syncthreads();
    }
    if (t < nb) g_boff[t] = x - v;    // exclusive
}

__global__ void k_scan3(int n, int E) {
    int i = blockIdx.x * blockDim.x + threadIdx.x;
    if (i < n)
        g_rowptr[i] += g_boff[i >> 10];
    if (i == 0) g_rowptr[n] = E;
}

// atomic-free scatter: slot = rowptr[dst] + rank[e]
__global__ void k_scatter(const int* __restrict__ ei, const float* __restrict__ ea,
                          int E, int n) {
    for (int e = blockIdx.x * blockDim.x + threadIdx.x; e < E; e += gridDim.x * blockDim.x) {
        int s = clampi(ei[e], n);
        int d = clampi(ei[E + e], n);
        g_csr[g_rowptr[d] + g_rank[e]] = make_int2(s, __float_as_int(ea[e]));
    }
}

// ---------------------------------------------------------------------------
// transform: h = in @ W (layer2 input = relu(g_out + b1)); emits asrc/adst.
// Mapping: warp = 4-column quad (broadcast LDS.128 on W), lane = node.
template <int FIN, bool SECOND>
__global__ void k_transform(const float* __restrict__ xin,
                            const float* __restrict__ W,
                            const float* __restrict__ a_src,
                            const float* __restrict__ a_dst,
                            const float* __restrict__ bias, int n) {
    __shared__ float W_sh[FIN * 32];
    __shared__ float x_sh[32][FIN + 1];
    __shared__ float s_as[32], s_ad[32], s_b[32];
    __shared__ float sm_ps[8][32], sm_pd[8][32];
    int tid = threadIdx.x;
    for (int i = tid; i < FIN * 32; i += 256) W_sh[i] = W[i];
    if (tid < 32) {
        s_as[tid] = a_src[tid];
        s_ad[tid] = a_dst[tid];
        s_b[tid] = SECOND ? bias[tid] : 0.f;
    }
    __syncthreads();
    int nb = blockIdx.x * 32;
    for (int i = tid; i < 32 * FIN; i += 256) {
        int r = i / FIN, c = i % FIN;
        int node = nb + r;
        float v = 0.f;
        if (node < n)
            v = SECOND ? fmaxf(g_out[node * 32 + c] + s_b[c], 0.f)
                       : xin[(size_t)node * FIN + c];
        x_sh[r][c] = v;
    }
    __syncthreads();

    int w = tid >> 5, lane = tid & 31;
    int node = nb + lane;
    float4 acc = make_float4(0.f, 0.f, 0.f, 0.f);
    const float4* W4 = (const float4*)W_sh;
    #pragma unroll 8
    for (int k = 0; k < FIN; k++) {
        float4 wv = W4[k * 8 + w];     // same addr across warp -> broadcast
        float xv = x_sh[lane][k];      // conflict-free (stride FIN+1)
        acc.x = fmaf(xv, wv.x, acc.x);
        acc.y = fmaf(xv, wv.y, acc.y);
        acc.z = fmaf(xv, wv.z, acc.z);
        acc.w = fmaf(xv, wv.w, acc.w);
    }
    if (node < n)
        ((float4*)(g_h + node * 32))[w] = acc;

    sm_ps[w][lane] = acc.x * s_as[w * 4]     + acc.y * s_as[w * 4 + 1]
                   + acc.z * s_as[w * 4 + 2] + acc.w * s_as[w * 4 + 3];
    sm_pd[w][lane] = acc.x * s_ad[w * 4]     + acc.y * s_ad[w * 4 + 1]
                   + acc.z * s_ad[w * 4 + 2] + acc.w * s_ad[w * 4 + 3];
    __syncthreads();
    if (tid < 64) {
        int l = tid & 31, hh = tid >> 5;
        int node2 = nb + l;
        if (node2 < n) {
            int wb = hh * 4;
            float vs = sm_ps[wb][l] + sm_ps[wb + 1][l] + sm_ps[wb + 2][l] + sm_ps[wb + 3][l];
            float vd = sm_pd[wb][l] + sm_pd[wb + 1][l] + sm_pd[wb + 2][l] + sm_pd[wb + 3][l];
            g_asrc[node2 * 2 + hh] = vs;
            g_adst[node2 * 2 + hh] = vd;
        }
    }
}

// ---------------------------------------------------------------------------
// fused aggregation: warp per dst node, no atomics on features.
// Always reads transformed features from g_h (both layers).
// LAYER==0: write g_out.  LAYER==1: fused mean-pool accumulation (+b2).
template <int LAYER>
__global__ void k_agg(int n, const int* __restrict__ batch,
                      const float* __restrict__ b2, int G) {
    int wg = (blockIdx.x * blockDim.x + threadIdx.x) >> 5;
    if (wg >= n) return;
    int lane = threadIdx.x & 31;
    int node = wg;
    float c0 = g_scal[2 + LAYER * 2];
    float c1 = g_scal[3 + LAYER * 2];
    float mean = g_scal[1];
    float2 ad = ((const float2*)g_adst)[node];
    bool hi = lane >= 16;

    float acc = 0.f, s0 = 0.f, s1 = 0.f;
    int beg = g_rowptr[node], end = g_rowptr[node + 1];

    for (int j0 = beg; j0 < end; j0 += 32) {
        int j = j0 + lane;
        bool v = j < end;
        int src = node;
        float av = 0.f;
        if (v) {
            int2 p = g_csr[j];
            src = p.x;
            av = __int_as_float(p.y);
        }
        float2 as = ((const float2*)g_asrc)[src];
        float a0 = as.x + ad.x + av * c0;
        float a1 = as.y + ad.y + av * c1;
        a0 = a0 > 0.f ? a0 : 0.2f * a0;
        a1 = a1 > 0.f ? a1 : 0.2f * a1;
        float ex0 = v ? __expf(a0) : 0.f;
        float ex1 = v ? __expf(a1) : 0.f;
        s0 += ex0;
        s1 += ex1;
        if (end - j0 >= 32) {
            #pragma unroll
            for (int t = 0; t < 32; t++) {
                int st = __shfl_sync(0xffffffffu, src, t);
                float e0 = __shfl_sync(0xffffffffu, ex0, t);
                float e1 = __shfl_sync(0xffffffffu, ex1, t);
                acc = fmaf(g_h[st * 32 + lane], hi ? e1 : e0, acc);
            }
        } else {
            int cnt = end - j0;
            for (int t = 0; t < cnt; t++) {
                int st = __shfl_sync(0xffffffffu, src, t);
                float e0 = __shfl_sync(0xffffffffu, ex0, t);
                float e1 = __shfl_sync(0xffffffffu, ex1, t);
                acc = fmaf(g_h[st * 32 + lane], hi ? e1 : e0, acc);
            }
        }
    }

    // self loop (src = node, ea = mean)
    {
        float2 as = ((const float2*)g_asrc)[node];
        float a0 = as.x + ad.x + mean * c0;
        float a1 = as.y + ad.y + mean * c1;
        a0 = a0 > 0.f ? a0 : 0.2f * a0;
        a1 = a1 > 0.f ? a1 : 0.2f * a1;
        float ex0 = __expf(a0), ex1 = __expf(a1);
        if (lane == 0) { s0 += ex0; s1 += ex1; }
        acc = fmaf(g_h[node * 32 + lane], hi ? ex1 : ex0, acc);
    }

    #pragma unroll
    for (int off = 16; off; off >>= 1) {
        s0 += __shfl_xor_sync(0xffffffffu, s0, off);
        s1 += __shfl_xor_sync(0xffffffffu, s1, off);
    }
    float s = hi ? s1 : s0;
    float o = acc / (s + 1e-16f);

    if (LAYER == 0) {
        g_out[node * 32 + lane] = o;
    } else {
        int g = clampi(batch[node], G);
        atomicAdd(&g_pool[g * 32 + lane], o + b2[lane]);
        if (lane == 0) atomicAdd(&g_cnt[g], 1.f);
    }
}

// ---------------------------------------------------------------------------
__global__ void k_mlp(float* __restrict__ out,
                      const float* __restrict__ Wf1, const float* __restrict__ bf1,
                      const float* __restrict__ Wf2, const float* __restrict__ bf2, int G) {
    int g = blockIdx.x * blockDim.x + threadIdx.x;
    if (g >= G) return;
    float inv = 1.f / fmaxf(g_cnt[g], 1.f);
    float emb[32];
    #pragma unroll
    for (int i = 0; i < 32; i++) emb[i] = g_pool[g * 32 + i] * inv;
    float o0 = bf2[0], o1 = bf2[1];
    for (int j = 0; j < 32; j++) {
        float z = bf1[j];
        #pragma unroll
        for (int i = 0; i < 32; i++) z = fmaf(emb[i], Wf1[i * 32 + j], z);
        z = fmaxf(z, 0.f);
        o0 = fmaf(z, Wf2[j * 2], o0);
        o1 = fmaf(z, Wf2[j * 2 + 1], o1);
    }
    out[g * 2] = o0;
    out[g * 2 + 1] = o1;
}

// ---------------------------------------------------------------------------
extern "C" void kernel_launch(void* const* d_in, const int* in_sizes, int n_in,
                              void* d_out, int out_size) {
    const float* x     = (const float*)d_in[0];
    const int*   ei    = (const int*)d_in[1];
    const float* ea    = (const float*)d_in[2];
    const int*   batch = (const int*)d_in[3];
    const float* W1  = (const float*)d_in[4];
    const float* as1 = (const float*)d_in[5];
    const float* ad1 = (const float*)d_in[6];
    const float* We1 = (const float*)d_in[7];
    const float* ae1 = (const float*)d_in[8];
    const float* b1  = (const float*)d_in[9];
    const float* W2  = (const float*)d_in[10];
    const float* as2 = (const float*)d_in[11];
    const float* ad2 = (const float*)d_in[12];
    const float* We2 = (const float*)d_in[13];
    const float* ae2 = (const float*)d_in[14];
    const float* b2  = (const float*)d_in[15];
    const float* Wf1 = (const float*)d_in[16];
    const float* bf1 = (const float*)d_in[17];
    const float* Wf2 = (const float*)d_in[18];
    const float* bf2 = (const float*)d_in[19];

    int N = in_sizes[0] / 128;
    int E = in_sizes[1] / 2;
    int G = out_size / 2;
    int nb = (N + 1023) / 1024;
    int tb = (N + 31) / 32;
    int ab = (N + 7) / 8;

    k_init<<<128, 1024>>>(N);
    k_hist<<<2048, 256>>>(ei, ea, E, N);
    k_prep<<<1, 32>>>(We1, ae1, We2, ae2, E);

    k_scan1<<<nb, 1024>>>(N);
    k_scan2<<<1, 1024>>>(nb);
    k_scan3<<<(N + 1023) / 1024, 1024>>>(N, E);
    k_scatter<<<2048, 512>>>(ei, ea, E, N);

    // layer 1
    k_transform<128, false><<<tb, 256>>>(x, W1, as1, ad1, nullptr, N);
    k_agg<0><<<ab, 256>>>(N, nullptr, nullptr, G);

    // layer 2 (input = relu(g_out + b1)); pool fused into agg
    k_transform<32, true><<<tb, 256>>>(nullptr, W2, as2, ad2, b1, N);
    k_agg<1><<<ab, 256>>>(N, batch, b2, G);

    k_mlp<<<1, 64>>>((float*)d_out, Wf1, bf1, Wf2, bf2, G);
}

// round 7
// speedup vs baseline: 2.0898x; 1.0524x over previous
#include <cuda_runtime.h>

// ---------------------------------------------------------------------------
// GAT (2 layers, edge features, H=2 heads x C=16) + mean pool + MLP -> [G,2]
// dst-CSR built once (rank captured in histogram); atomic-free warp-per-node
// aggregation with smem edge staging; layer-2 transform fused into agg0
// epilogue (double-buffered); pool fused into agg1.
// ---------------------------------------------------------------------------

#define MAXN 100352
#define MAXE 3211264
#define MAXG 256
#define NBS ((MAXN + 1023) / 1024)

__device__ __align__(16) float g_h[MAXN * 32];      // layer-1 transformed features
__device__ __align__(16) float g_out[MAXN * 32];    // layer-2 transformed features
__device__ __align__(16) float g_asrc[MAXN * 2];
__device__ __align__(16) float g_adst[MAXN * 2];
__device__ __align__(16) float g_asrc2[MAXN * 2];
__device__ __align__(16) float g_adst2[MAXN * 2];
__device__ __align__(16) int2  g_csr[MAXE];         // (src, ea_bits), dst-sorted
__device__ int g_rank[MAXE];
__device__ int g_rowptr[MAXN + 1];
__device__ int g_deg[MAXN];
__device__ int g_bsum[NBS];
__device__ int g_boff[NBS];
__device__ __align__(16) float g_scal[8];           // [0]=esum [1]=mean [2..5]=ce
__device__ __align__(16) float g_pool[MAXG * 32];
__device__ float g_cnt[MAXG];

__device__ __forceinline__ int clampi(int v, int hi) {
    return v < 0 ? 0 : (v >= hi ? hi - 1 : v);
}

// ---------------------------------------------------------------------------
__global__ void k_init(int n) {
    int stride = gridDim.x * blockDim.x;
    for (int i = blockIdx.x * blockDim.x + threadIdx.x; i < n; i += stride)
        g_deg[i] = 0;
    int t = blockIdx.x * blockDim.x + threadIdx.x;
    if (t < 8) g_scal[t] = 0.f;
    if (t < MAXG) g_cnt[t] = 0.f;
    if (t < MAXG * 32) g_pool[t] = 0.f;
}

// histogram (captures per-edge rank) + edge_attr sum in one pass
__global__ void k_hist(const int* __restrict__ ei, const float* __restrict__ ea,
                       int E, int n) {
    __shared__ float red[256];
    float acc = 0.f;
    for (int e = blockIdx.x * 256 + threadIdx.x; e < E; e += gridDim.x * 256) {
        int d = clampi(ei[E + e], n);
        g_rank[e] = atomicAdd(&g_deg[d], 1);
        acc += ea[e];
    }
    red[threadIdx.x] = acc;
    __syncthreads();
    for (int s = 128; s; s >>= 1) {
        if (threadIdx.x < s) red[threadIdx.x] += red[threadIdx.x + s];
        __syncthreads();
    }
    if (threadIdx.x == 0) atomicAdd(&g_scal[0], red[0]);
}

__global__ void k_prep(const float* __restrict__ We1, const float* __restrict__ ae1,
                       const float* __restrict__ We2, const float* __restrict__ ae2, int E) {
    int t = threadIdx.x;
    if (t == 0) g_scal[1] = g_scal[0] / (float)E;
    if (t < 4) {
        int layer = t >> 1, hh = t & 1;
        const float* We = layer ? We2 : We1;
        const float* ae = layer ? ae2 : ae1;
        float c = 0.f;
        for (int i = 0; i < 16; i++) c += We[hh * 16 + i] * ae[hh * 16 + i];
        g_scal[2 + layer * 2 + hh] = c;
    }
}

// ---------------------------------------------------------------------------
__global__ void k_scan1(int n) {
    __shared__ int sm[1024];
    int t = threadIdx.x;
    int i = blockIdx.x * 1024 + t;
    int v = (i < n) ? g_deg[i] : 0;
    int x = v;
    sm[t] = x;
    __syncthreads();
    #pragma unroll
    for (int off = 1; off < 1024; off <<= 1) {
        int y = (t >= off) ? sm[t - off] : 0;
        __syncthreads();
        x += y;
        sm[t] = x;
        __syncthreads();
    }
    if (i < n) g_rowptr[i] = x - v;   // exclusive, pre-offset
    if (t == 1023) g_bsum[blockIdx.x] = x;
}

__global__ void k_scan2(int nb) {
    __shared__ int sm[1024];
    int t = threadIdx.x;
    int v = (t < nb) ? g_bsum[t] : 0;
    int x = v;
    sm[t] = x;
    __syncthreads();
    #pragma unroll
    for (int off = 1; off < 1024; off <<= 1) {
        int y = (t >= off) ? sm[t - off] : 0;
        __syncthreads();
        x += y;
        sm[t] = x;
        __syncthreads();
    }
    if (t < nb) g_boff[t] = x - v;    // exclusive
}

__global__ void k_scan3(int n, int E) {
    int i = blockIdx.x * blockDim.x + threadIdx.x;
    if (i < n)
        g_rowptr[i] += g_boff[i >> 10];
    if (i == 0) g_rowptr[n] = E;
}

// atomic-free scatter: slot = rowptr[dst] + rank[e]
__global__ void k_scatter(const int* __restrict__ ei, const float* __restrict__ ea,
                          int E, int n) {
    for (int e = blockIdx.x * blockDim.x + threadIdx.x; e < E; e += gridDim.x * blockDim.x) {
        int s = clampi(ei[e], n);
        int d = clampi(ei[E + e], n);
        g_csr[g_rowptr[d] + g_rank[e]] = make_int2(s, __float_as_int(ea[e]));
    }
}

// ---------------------------------------------------------------------------
// layer-1 transform: h = x @ W1; emits asrc/adst.
// Mapping: warp = 4-column quad (broadcast LDS.128 on W), lane = node.
__global__ void k_transform1(const float* __restrict__ xin,
                             const float* __restrict__ W,
                             const float* __restrict__ a_src,
                             const float* __restrict__ a_dst, int n) {
    constexpr int FIN = 128;
    __shared__ float W_sh[FIN * 32];
    __shared__ float x_sh[32][FIN + 1];
    __shared__ float s_as[32], s_ad[32];
    __shared__ float sm_ps[8][32], sm_pd[8][32];
    int tid = threadIdx.x;
    for (int i = tid; i < FIN * 32; i += 256) W_sh[i] = W[i];
    if (tid < 32) {
        s_as[tid] = a_src[tid];
        s_ad[tid] = a_dst[tid];
    }
    __syncthreads();
    int nb = blockIdx.x * 32;
    for (int i = tid; i < 32 * FIN; i += 256) {
        int r = i / FIN, c = i % FIN;
        int node = nb + r;
        x_sh[r][c] = (node < n) ? xin[(size_t)node * FIN + c] : 0.f;
    }
    __syncthreads();

    int w = tid >> 5, lane = tid & 31;
    int node = nb + lane;
    float4 acc = make_float4(0.f, 0.f, 0.f, 0.f);
    const float4* W4 = (const float4*)W_sh;
    #pragma unroll 8
    for (int k = 0; k < FIN; k++) {
        float4 wv = W4[k * 8 + w];     // same addr across warp -> broadcast
        float xv = x_sh[lane][k];      // conflict-free (stride FIN+1)
        acc.x = fmaf(xv, wv.x, acc.x);
        acc.y = fmaf(xv, wv.y, acc.y);
        acc.z = fmaf(xv, wv.z, acc.z);
        acc.w = fmaf(xv, wv.w, acc.w);
    }
    if (node < n)
        ((float4*)(g_h + node * 32))[w] = acc;

    sm_ps[w][lane] = acc.x * s_as[w * 4]     + acc.y * s_as[w * 4 + 1]
                   + acc.z * s_as[w * 4 + 2] + acc.w * s_as[w * 4 + 3];
    sm_pd[w][lane] = acc.x * s_ad[w * 4]     + acc.y * s_ad[w * 4 + 1]
                   + acc.z * s_ad[w * 4 + 2] + acc.w * s_ad[w * 4 + 3];
    __syncthreads();
    if (tid < 64) {
        int l = tid & 31, hh = tid >> 5;
        int node2 = nb + l;
        if (node2 < n) {
            int wb = hh * 4;
            float vs = sm_ps[wb][l] + sm_ps[wb + 1][l] + sm_ps[wb + 2][l] + sm_ps[wb + 3][l];
            float vd = sm_pd[wb][l] + sm_pd[wb + 1][l] + sm_pd[wb + 2][l] + sm_pd[wb + 3][l];
            g_asrc[node2 * 2 + hh] = vs;
            g_adst[node2 * 2 + hh] = vd;
        }
    }
}

// ---------------------------------------------------------------------------
// fused aggregation: warp per dst node, no feature atomics, smem edge staging.
// LAYER==0: features g_h/asrc/adst; epilogue = layer-2 transform
//           (relu(o+b1) @ W2) -> g_out, g_asrc2/g_adst2.
// LAYER==1: features g_out/asrc2/adst2; epilogue = mean-pool accumulation (+b2).
template <int LAYER>
__global__ void k_agg(int n,
                      const float* __restrict__ W2, const float* __restrict__ b1,
                      const float* __restrict__ as2, const float* __restrict__ ad2,
                      const int* __restrict__ batch, const float* __restrict__ b2,
                      int G) {
    __shared__ float4 stage[8][32];
    __shared__ float W2s[32 * 32];
    __shared__ float b1s[32], as2s[32], ad2s[32];
    int tid = threadIdx.x;
    if (LAYER == 0) {
        for (int i = tid; i < 1024; i += 256) W2s[i] = W2[i];
        if (tid < 32) {
            b1s[tid] = b1[tid];
            as2s[tid] = as2[tid];
            ad2s[tid] = ad2[tid];
        }
        __syncthreads();
    }

    int wg = (blockIdx.x * blockDim.x + tid) >> 5;
    if (wg >= n) return;
    int w = tid >> 5, lane = tid & 31;
    int node = wg;
    float c0 = g_scal[2 + LAYER * 2];
    float c1 = g_scal[3 + LAYER * 2];
    float mean = g_scal[1];
    const float* hf   = LAYER ? g_out  : g_h;
    const float* asrc = LAYER ? g_asrc2 : g_asrc;
    const float* adst = LAYER ? g_adst2 : g_adst;
    float2 ad = ((const float2*)adst)[node];
    bool hi = lane >= 16;

    float acc = 0.f, s0 = 0.f, s1 = 0.f;
    int beg = g_rowptr[node], end = g_rowptr[node + 1];

    for (int j0 = beg; j0 < end; j0 += 32) {
        int j = j0 + lane;
        bool v = j < end;
        int src = node;
        float av = 0.f;
        if (v) {
            int2 p = g_csr[j];
            src = p.x;
            av = __int_as_float(p.y);
        }
        float2 as = ((const float2*)asrc)[src];
        float a0 = as.x + ad.x + av * c0;
        float a1 = as.y + ad.y + av * c1;
        a0 = a0 > 0.f ? a0 : 0.2f * a0;
        a1 = a1 > 0.f ? a1 : 0.2f * a1;
        float ex0 = v ? __expf(a0) : 0.f;
        float ex1 = v ? __expf(a1) : 0.f;
        s0 += ex0;
        s1 += ex1;
        stage[w][lane] = make_float4(__int_as_float(src), ex0, ex1, 0.f);
        __syncwarp();
        if (end - j0 >= 32) {
            #pragma unroll
            for (int t = 0; t < 32; t++) {
                float4 p = stage[w][t];                 // broadcast LDS.128
                acc = fmaf(hf[__float_as_int(p.x) * 32 + lane], hi ? p.z : p.y, acc);
            }
        } else {
            int cnt = end - j0;
            for (int t = 0; t < cnt; t++) {
                float4 p = stage[w][t];
                acc = fmaf(hf[__float_as_int(p.x) * 32 + lane], hi ? p.z : p.y, acc);
            }
        }
        __syncwarp();
    }

    // self loop (src = node, ea = mean)
    {
        float2 as = ((const float2*)asrc)[node];
        float a0 = as.x + ad.x + mean * c0;
        float a1 = as.y + ad.y + mean * c1;
        a0 = a0 > 0.f ? a0 : 0.2f * a0;
        a1 = a1 > 0.f ? a1 : 0.2f * a1;
        float ex0 = __expf(a0), ex1 = __expf(a1);
        if (lane == 0) { s0 += ex0; s1 += ex1; }
        acc = fmaf(hf[node * 32 + lane], hi ? ex1 : ex0, acc);
    }

    #pragma unroll
    for (int off = 16; off; off >>= 1) {
        s0 += __shfl_xor_sync(0xffffffffu, s0, off);
        s1 += __shfl_xor_sync(0xffffffffu, s1, off);
    }
    float s = hi ? s1 : s0;
    float o = acc / (s + 1e-16f);

    if (LAYER == 0) {
        // fused layer-2 transform: x2 = relu(o + b1); h2 = x2 @ W2
        float* xrow = (float*)&stage[w][0];
        xrow[lane] = fmaxf(o + b1s[lane], 0.f);
        __syncwarp();
        float acc2 = 0.f;
        #pragma unroll 8
        for (int k = 0; k < 32; k++)
            acc2 = fmaf(xrow[k], W2s[k * 32 + lane], acc2);   // bcast LDS + cf LDS
        g_out[node * 32 + lane] = acc2;
        float ps = acc2 * as2s[lane];
        float pd = acc2 * ad2s[lane];
        #pragma unroll
        for (int off = 8; off; off >>= 1) {
            ps += __shfl_down_sync(0xffffffffu, ps, off, 16);
            pd += __shfl_down_sync(0xffffffffu, pd, off, 16);
        }
        if ((lane & 15) == 0) {
            int hh = lane >> 4;
            g_asrc2[node * 2 + hh] = ps;
            g_adst2[node * 2 + hh] = pd;
        }
    } else {
        int g = clampi(batch[node], G);
        atomicAdd(&g_pool[g * 32 + lane], o + b2[lane]);
        if (lane == 0) atomicAdd(&g_cnt[g], 1.f);
    }
}

// ---------------------------------------------------------------------------
__global__ void k_mlp(float* __restrict__ out,
                      const float* __restrict__ Wf1, const float* __restrict__ bf1,
                      const float* __restrict__ Wf2, const float* __restrict__ bf2, int G) {
    int g = blockIdx.x * blockDim.x + threadIdx.x;
    if (g >= G) return;
    float inv = 1.f / fmaxf(g_cnt[g], 1.f);
    float emb[32];
    #pragma unroll
    for (int i = 0; i < 32; i++) emb[i] = g_pool[g * 32 + i] * inv;
    float o0 = bf2[0], o1 = bf2[1];
    for (int j = 0; j < 32; j++) {
        float z = bf1[j];
        #pragma unroll
        for (int i = 0; i < 32; i++) z = fmaf(emb[i], Wf1[i * 32 + j], z);
        z = fmaxf(z, 0.f);
        o0 = fmaf(z, Wf2[j * 2], o0);
        o1 = fmaf(z, Wf2[j * 2 + 1], o1);
    }
    out[g * 2] = o0;
    out[g * 2 + 1] = o1;
}

// ---------------------------------------------------------------------------
extern "C" void kernel_launch(void* const* d_in, const int* in_sizes, int n_in,
                              void* d_out, int out_size) {
    const float* x     = (const float*)d_in[0];
    const int*   ei    = (const int*)d_in[1];
    const float* ea    = (const float*)d_in[2];
    const int*   batch = (const int*)d_in[3];
    const float* W1  = (const float*)d_in[4];
    const float* as1 = (const float*)d_in[5];
    const float* ad1 = (const float*)d_in[6];
    const float* We1 = (const float*)d_in[7];
    const float* ae1 = (const float*)d_in[8];
    const float* b1  = (const float*)d_in[9];
    const float* W2  = (const float*)d_in[10];
    const float* as2 = (const float*)d_in[11];
    const float* ad2 = (const float*)d_in[12];
    const float* We2 = (const float*)d_in[13];
    const float* ae2 = (const float*)d_in[14];
    const float* b2  = (const float*)d_in[15];
    const float* Wf1 = (const float*)d_in[16];
    const float* bf1 = (const float*)d_in[17];
    const float* Wf2 = (const float*)d_in[18];
    const float* bf2 = (const float*)d_in[19];

    int N = in_sizes[0] / 128;
    int E = in_sizes[1] / 2;
    int G = out_size / 2;
    int nb = (N + 1023) / 1024;
    int tb = (N + 31) / 32;
    int ab = (N + 7) / 8;

    k_init<<<128, 1024>>>(N);
    k_hist<<<2048, 256>>>(ei, ea, E, N);
    k_prep<<<1, 32>>>(We1, ae1, We2, ae2, E);

    k_scan1<<<nb, 1024>>>(N);
    k_scan2<<<1, 1024>>>(nb);
    k_scan3<<<(N + 1023) / 1024, 1024>>>(N, E);
    k_scatter<<<2048, 512>>>(ei, ea, E, N);

    // layer 1 transform, then agg0 (with fused layer-2 transform epilogue)
    k_transform1<<<tb, 256>>>(x, W1, as1, ad1, N);
    k_agg<0><<<ab, 256>>>(N, W2, b1, as2, ad2, nullptr, nullptr, G);

    // layer 2 aggregation with fused mean-pool
    k_agg<1><<<ab, 256>>>(N, nullptr, nullptr, nullptr, nullptr, batch, b2, G);

    k_mlp<<<1, 64>>>((float*)d_out, Wf1, bf1, Wf2, bf2, G);
}

// round 8
// speedup vs baseline: 2.1880x; 1.0470x over previous
#include <cuda_runtime.h>

// ---------------------------------------------------------------------------
// GAT (2 layers, edge features, H=2 heads x C=16) + mean pool + MLP -> [G,2]
// dst-CSR built once; atomic-free warp-per-node aggregation, 2 edges per
// iteration (half-warp each, float2 columns); layer-2 transform fused into
// agg0 epilogue; pool fused into agg1.
// ---------------------------------------------------------------------------

#define MAXN 100352
#define MAXE 3211264
#define MAXG 256
#define NBS ((MAXN + 1023) / 1024)

__device__ __align__(16) float g_h[MAXN * 32];      // layer-1 transformed features
__device__ __align__(16) float g_out[MAXN * 32];    // layer-2 transformed features
__device__ __align__(16) float g_asrc[MAXN * 2];
__device__ __align__(16) float g_adst[MAXN * 2];
__device__ __align__(16) float g_asrc2[MAXN * 2];
__device__ __align__(16) float g_adst2[MAXN * 2];
__device__ __align__(16) int2  g_csr[MAXE];         // (src, ea_bits), dst-sorted
__device__ int g_rank[MAXE];
__device__ int g_rowptr[MAXN + 1];
__device__ int g_deg[MAXN];
__device__ int g_bsum[NBS];
__device__ int g_boff[NBS];
__device__ __align__(16) float g_scal[8];           // [0]=esum [1]=mean [2..5]=ce
__device__ __align__(16) float g_pool[MAXG * 32];
__device__ float g_cnt[MAXG];

__device__ __forceinline__ int clampi(int v, int hi) {
    return v < 0 ? 0 : (v >= hi ? hi - 1 : v);
}

// ---------------------------------------------------------------------------
__global__ void k_init(int n) {
    int stride = gridDim.x * blockDim.x;
    for (int i = blockIdx.x * blockDim.x + threadIdx.x; i < n; i += stride)
        g_deg[i] = 0;
    int t = blockIdx.x * blockDim.x + threadIdx.x;
    if (t < 8) g_scal[t] = 0.f;
    if (t < MAXG) g_cnt[t] = 0.f;
    if (t < MAXG * 32) g_pool[t] = 0.f;
}

// histogram (captures per-edge rank) + edge_attr sum in one pass
__global__ void k_hist(const int* __restrict__ ei, const float* __restrict__ ea,
                       int E, int n) {
    __shared__ float red[256];
    float acc = 0.f;
    for (int e = blockIdx.x * 256 + threadIdx.x; e < E; e += gridDim.x * 256) {
        int d = clampi(ei[E + e], n);
        g_rank[e] = atomicAdd(&g_deg[d], 1);
        acc += ea[e];
    }
    red[threadIdx.x] = acc;
    __syncthreads();
    for (int s = 128; s; s >>= 1) {
        if (threadIdx.x < s) red[threadIdx.x] += red[threadIdx.x + s];
        __syncthreads();
    }
    if (threadIdx.x == 0) atomicAdd(&g_scal[0], red[0]);
}

__global__ void k_prep(const float* __restrict__ We1, const float* __restrict__ ae1,
                       const float* __restrict__ We2, const float* __restrict__ ae2, int E) {
    int t = threadIdx.x;
    if (t == 0) g_scal[1] = g_scal[0] / (float)E;
    if (t < 4) {
        int layer = t >> 1, hh = t & 1;
        const float* We = layer ? We2 : We1;
        const float* ae = layer ? ae2 : ae1;
        float c = 0.f;
        for (int i = 0; i < 16; i++) c += We[hh * 16 + i] * ae[hh * 16 + i];
        g_scal[2 + layer * 2 + hh] = c;
    }
}

// ---------------------------------------------------------------------------
__global__ void k_scan1(int n) {
    __shared__ int sm[1024];
    int t = threadIdx.x;
    int i = blockIdx.x * 1024 + t;
    int v = (i < n) ? g_deg[i] : 0;
    int x = v;
    sm[t] = x;
    __syncthreads();
    #pragma unroll
    for (int off = 1; off < 1024; off <<= 1) {
        int y = (t >= off) ? sm[t - off] : 0;
        __syncthreads();
        x += y;
        sm[t] = x;
        __syncthreads();
    }
    if (i < n) g_rowptr[i] = x - v;   // exclusive, pre-offset
    if (t == 1023) g_bsum[blockIdx.x] = x;
}

__global__ void k_scan2(int nb) {
    __shared__ int sm[1024];
    int t = threadIdx.x;
    int v = (t < nb) ? g_bsum[t] : 0;
    int x = v;
    sm[t] = x;
    __syncthreads();
    #pragma unroll
    for (int off = 1; off < 1024; off <<= 1) {
        int y = (t >= off) ? sm[t - off] : 0;
        __syncthreads();
        x += y;
        sm[t] = x;
        __syncthreads();
    }
    if (t < nb) g_boff[t] = x - v;    // exclusive
}

__global__ void k_scan3(int n, int E) {
    int i = blockIdx.x * blockDim.x + threadIdx.x;
    if (i < n)
        g_rowptr[i] += g_boff[i >> 10];
    if (i == 0) g_rowptr[n] = E;
}

// atomic-free scatter: slot = rowptr[dst] + rank[e]
__global__ void k_scatter(const int* __restrict__ ei, const float* __restrict__ ea,
                          int E, int n) {
    for (int e = blockIdx.x * blockDim.x + threadIdx.x; e < E; e += gridDim.x * blockDim.x) {
        int s = clampi(ei[e], n);
        int d = clampi(ei[E + e], n);
        g_csr[g_rowptr[d] + g_rank[e]] = make_int2(s, __float_as_int(ea[e]));
    }
}

// ---------------------------------------------------------------------------
// layer-1 transform: h = x @ W1; emits asrc/adst.
__global__ void k_transform1(const float* __restrict__ xin,
                             const float* __restrict__ W,
                             const float* __restrict__ a_src,
                             const float* __restrict__ a_dst, int n) {
    constexpr int FIN = 128;
    __shared__ float W_sh[FIN * 32];
    __shared__ float x_sh[32][FIN + 1];
    __shared__ float s_as[32], s_ad[32];
    __shared__ float sm_ps[8][32], sm_pd[8][32];
    int tid = threadIdx.x;
    for (int i = tid; i < FIN * 32; i += 256) W_sh[i] = W[i];
    if (tid < 32) {
        s_as[tid] = a_src[tid];
        s_ad[tid] = a_dst[tid];
    }
    __syncthreads();
    int nb = blockIdx.x * 32;
    for (int i = tid; i < 32 * FIN; i += 256) {
        int r = i / FIN, c = i % FIN;
        int node = nb + r;
        x_sh[r][c] = (node < n) ? xin[(size_t)node * FIN + c] : 0.f;
    }
    __syncthreads();

    int w = tid >> 5, lane = tid & 31;
    int node = nb + lane;
    float4 acc = make_float4(0.f, 0.f, 0.f, 0.f);
    const float4* W4 = (const float4*)W_sh;
    #pragma unroll 8
    for (int k = 0; k < FIN; k++) {
        float4 wv = W4[k * 8 + w];     // same addr across warp -> broadcast
        float xv = x_sh[lane][k];      // conflict-free (stride FIN+1)
        acc.x = fmaf(xv, wv.x, acc.x);
        acc.y = fmaf(xv, wv.y, acc.y);
        acc.z = fmaf(xv, wv.z, acc.z);
        acc.w = fmaf(xv, wv.w, acc.w);
    }
    if (node < n)
        ((float4*)(g_h + node * 32))[w] = acc;

    sm_ps[w][lane] = acc.x * s_as[w * 4]     + acc.y * s_as[w * 4 + 1]
                   + acc.z * s_as[w * 4 + 2] + acc.w * s_as[w * 4 + 3];
    sm_pd[w][lane] = acc.x * s_ad[w * 4]     + acc.y * s_ad[w * 4 + 1]
                   + acc.z * s_ad[w * 4 + 2] + acc.w * s_ad[w * 4 + 3];
    __syncthreads();
    if (tid < 64) {
        int l = tid & 31, hh = tid >> 5;
        int node2 = nb + l;
        if (node2 < n) {
            int wb = hh * 4;
            float vs = sm_ps[wb][l] + sm_ps[wb + 1][l] + sm_ps[wb + 2][l] + sm_ps[wb + 3][l];
            float vd = sm_pd[wb][l] + sm_pd[wb + 1][l] + sm_pd[wb + 2][l] + sm_pd[wb + 3][l];
            g_asrc[node2 * 2 + hh] = vs;
            g_adst[node2 * 2 + hh] = vd;
        }
    }
}

// ---------------------------------------------------------------------------
// fused aggregation: warp per dst node; gather loop processes 2 edges per
// iteration (half-warp each, float2 column pairs).
// LAYER==0: features g_h/asrc/adst; epilogue = layer-2 transform -> g_out.
// LAYER==1: features g_out/asrc2/adst2; epilogue = mean-pool accumulation.
template <int LAYER>
__global__ void __launch_bounds__(256, 6)
k_agg(int n,
      const float* __restrict__ W2, const float* __restrict__ b1,
      const float* __restrict__ as2, const float* __restrict__ ad2,
      const int* __restrict__ batch, const float* __restrict__ b2,
      int G) {
    __shared__ float4 stage[8][32];
    __shared__ float W2s[32 * 32];
    __shared__ float b1s[32], as2s[32], ad2s[32];
    int tid = threadIdx.x;
    if (LAYER == 0) {
        for (int i = tid; i < 1024; i += 256) W2s[i] = W2[i];
        if (tid < 32) {
            b1s[tid] = b1[tid];
            as2s[tid] = as2[tid];
            ad2s[tid] = ad2[tid];
        }
        __syncthreads();
    }

    int wg = (blockIdx.x * blockDim.x + tid) >> 5;
    if (wg >= n) return;
    int w = tid >> 5, lane = tid & 31;
    int hl = lane & 15;            // half-warp lane -> column pair (2*hl, 2*hl+1)
    int node = wg;
    float c0 = g_scal[2 + LAYER * 2];
    float c1 = g_scal[3 + LAYER * 2];
    float mean = g_scal[1];
    const float*  hf   = LAYER ? g_out   : g_h;
    const float2* hf2  = (const float2*)hf;
    const float*  asrc = LAYER ? g_asrc2 : g_asrc;
    const float*  adst = LAYER ? g_adst2 : g_adst;
    float2 ad = ((const float2*)adst)[node];
    bool head1 = hl >= 8;          // column pair's head

    float2 acc = make_float2(0.f, 0.f);
    float s0 = 0.f, s1 = 0.f;
    int beg = g_rowptr[node], end = g_rowptr[node + 1];

    for (int j0 = beg; j0 < end; j0 += 32) {
        int j = j0 + lane;
        bool v = j < end;
        int src = node;
        float av = 0.f;
        if (v) {
            int2 p = g_csr[j];
            src = p.x;
            av = __int_as_float(p.y);
        }
        float2 as = ((const float2*)asrc)[src];
        float a0 = as.x + ad.x + av * c0;
        float a1 = as.y + ad.y + av * c1;
        a0 = a0 > 0.f ? a0 : 0.2f * a0;
        a1 = a1 > 0.f ? a1 : 0.2f * a1;
        float ex0 = v ? __expf(a0) : 0.f;   // invalid lanes stage ex=0
        float ex1 = v ? __expf(a1) : 0.f;
        s0 += ex0;
        s1 += ex1;
        stage[w][lane] = make_float4(__int_as_float(src), ex0, ex1, 0.f);
        __syncwarp();
        int cnt = min(end - j0, 32);
        int half = lane >> 4;               // 0: even edge, 1: odd edge
        if (cnt == 32) {
            #pragma unroll
            for (int t = 0; t < 32; t += 2) {
                float4 p = stage[w][t + half];            // LDS.128, 2 addrs
                float2 hv = hf2[__float_as_int(p.x) * 16 + hl];
                float e = head1 ? p.z : p.y;
                acc.x = fmaf(hv.x, e, acc.x);
                acc.y = fmaf(hv.y, e, acc.y);
            }
        } else {
            for (int t = 0; t < cnt; t += 2) {
                float4 p = stage[w][t + half];            // slot >= cnt has ex=0
                float2 hv = hf2[__float_as_int(p.x) * 16 + hl];
                float e = head1 ? p.z : p.y;
                acc.x = fmaf(hv.x, e, acc.x);
                acc.y = fmaf(hv.y, e, acc.y);
            }
        }
        __syncwarp();
    }

    // self loop (src = node, ea = mean) -- applied by lanes 0-15 only
    {
        float2 as = ((const float2*)asrc)[node];
        float a0 = as.x + ad.x + mean * c0;
        float a1 = as.y + ad.y + mean * c1;
        a0 = a0 > 0.f ? a0 : 0.2f * a0;
        a1 = a1 > 0.f ? a1 : 0.2f * a1;
        float ex0 = __expf(a0), ex1 = __expf(a1);
        if (lane == 0) { s0 += ex0; s1 += ex1; }
        float2 hv = hf2[node * 16 + hl];
        float e = (lane < 16) ? (head1 ? ex1 : ex0) : 0.f;
        acc.x = fmaf(hv.x, e, acc.x);
        acc.y = fmaf(hv.y, e, acc.y);
    }

    // combine half-warps (both halves hold same column pairs)
    acc.x += __shfl_down_sync(0xffffffffu, acc.x, 16);
    acc.y += __shfl_down_sync(0xffffffffu, acc.y, 16);

    #pragma unroll
    for (int off = 16; off; off >>= 1) {
        s0 += __shfl_xor_sync(0xffffffffu, s0, off);
        s1 += __shfl_xor_sync(0xffffffffu, s1, off);
    }
    float sinv = 1.f / ((head1 ? s1 : s0) + 1e-16f);
    float2 o2 = make_float2(acc.x * sinv, acc.y * sinv);   // valid in lanes 0-15

    if (LAYER == 0) {
        // fused layer-2 transform: x2 = relu(o + b1); h2 = x2 @ W2
        float* xrow = (float*)&stage[w][0];
        if (lane < 16) {
            xrow[2 * hl]     = fmaxf(o2.x + b1s[2 * hl], 0.f);
            xrow[2 * hl + 1] = fmaxf(o2.y + b1s[2 * hl + 1], 0.f);
        }
        __syncwarp();
        float acc2 = 0.f;
        #pragma unroll 8
        for (int k = 0; k < 32; k++)
            acc2 = fmaf(xrow[k], W2s[k * 32 + lane], acc2);
        g_out[node * 32 + lane] = acc2;
        float ps = acc2 * as2s[lane];
        float pd = acc2 * ad2s[lane];
        #pragma unroll
        for (int off = 8; off; off >>= 1) {
            ps += __shfl_down_sync(0xffffffffu, ps, off, 16);
            pd += __shfl_down_sync(0xffffffffu, pd, off, 16);
        }
        if ((lane & 15) == 0) {
            int hh = lane >> 4;
            g_asrc2[node * 2 + hh] = ps;
            g_adst2[node * 2 + hh] = pd;
        }
    } else {
        int g = clampi(batch[node], G);
        if (lane < 16) {
            float2 add = make_float2(o2.x + b2[2 * hl], o2.y + b2[2 * hl + 1]);
            atomicAdd((float2*)&g_pool[g * 32 + 2 * hl], add);
        }
        if (lane == 0) atomicAdd(&g_cnt[g], 1.f);
    }
}

// ---------------------------------------------------------------------------
__global__ void k_mlp(float* __restrict__ out,
                      const float* __restrict__ Wf1, const float* __restrict__ bf1,
                      const float* __restrict__ Wf2, const float* __restrict__ bf2, int G) {
    int g = blockIdx.x * blockDim.x + threadIdx.x;
    if (g >= G) return;
    float inv = 1.f / fmaxf(g_cnt[g], 1.f);
    float emb[32];
    #pragma unroll
    for (int i = 0; i < 32; i++) emb[i] = g_pool[g * 32 + i] * inv;
    float o0 = bf2[0], o1 = bf2[1];
    for (int j = 0; j < 32; j++) {
        float z = bf1[j];
        #pragma unroll
        for (int i = 0; i < 32; i++) z = fmaf(emb[i], Wf1[i * 32 + j], z);
        z = fmaxf(z, 0.f);
        o0 = fmaf(z, Wf2[j * 2], o0);
        o1 = fmaf(z, Wf2[j * 2 + 1], o1);
    }
    out[g * 2] = o0;
    out[g * 2 + 1] = o1;
}

// ---------------------------------------------------------------------------
extern "C" void kernel_launch(void* const* d_in, const int* in_sizes, int n_in,
                              void* d_out, int out_size) {
    const float* x     = (const float*)d_in[0];
    const int*   ei    = (const int*)d_in[1];
    const float* ea    = (const float*)d_in[2];
    const int*   batch = (const int*)d_in[3];
    const float* W1  = (const float*)d_in[4];
    const float* as1 = (const float*)d_in[5];
    const float* ad1 = (const float*)d_in[6];
    const float* We1 = (const float*)d_in[7];
    const float* ae1 = (const float*)d_in[8];
    const float* b1  = (const float*)d_in[9];
    const float* W2  = (const float*)d_in[10];
    const float* as2 = (const float*)d_in[11];
    const float* ad2 = (const float*)d_in[12];
    const float* We2 = (const float*)d_in[13];
    const float* ae2 = (const float*)d_in[14];
    const float* b2  = (const float*)d_in[15];
    const float* Wf1 = (const float*)d_in[16];
    const float* bf1 = (const float*)d_in[17];
    const float* Wf2 = (const float*)d_in[18];
    const float* bf2 = (const float*)d_in[19];

    int N = in_sizes[0] / 128;
    int E = in_sizes[1] / 2;
    int G = out_size / 2;
    int nb = (N + 1023) / 1024;
    int tb = (N + 31) / 32;
    int ab = (N + 7) / 8;

    k_init<<<128, 1024>>>(N);
    k_hist<<<2048, 256>>>(ei, ea, E, N);
    k_prep<<<1, 32>>>(We1, ae1, We2, ae2, E);

    k_scan1<<<nb, 1024>>>(N);
    k_scan2<<<1, 1024>>>(nb);
    k_scan3<<<(N + 1023) / 1024, 1024>>>(N, E);
    k_scatter<<<2048, 512>>>(ei, ea, E, N);

    // layer 1 transform, then agg0 (with fused layer-2 transform epilogue)
    k_transform1<<<tb, 256>>>(x, W1, as1, ad1, N);
    k_agg<0><<<ab, 256>>>(N, W2, b1, as2, ad2, nullptr, nullptr, G);

    // layer 2 aggregation with fused mean-pool
    k_agg<1><<<ab, 256>>>(N, nullptr, nullptr, nullptr, nullptr, batch, b2, G);

    k_mlp<<<1, 64>>>((float*)d_out, Wf1, bf1, Wf2, bf2, G);
}